// round 7
// baseline (speedup 1.0000x reference)
#include <cuda_runtime.h>

// LTC MemoryCell: B=32, T=128, d=128, units=256, ODE_UNFOLDS=6.
// Each (v[b,j], v[b,j+d]) pair is an independent 2-dim recurrence.
//
// R7: R3 math (tanh-form sigmoid + (num,D) carry), but TWO batches per thread.
// With 1 warp/SMSP the chain stalls were unfillable; the second independent
// pair (same j => same constants, only x-stream + 4-reg state differ) provides
// the ILP to fill them, driving cost/pair toward the MUFU port bound.

#define Dn      128
#define UNITS   256
#define Tn      128
#define UNFOLDS 6
#define EPSc    1e-8f

__device__ __forceinline__ float tanhf_(float x) {
    float y; asm("tanh.approx.f32 %0, %1;" : "=f"(y) : "f"(x)); return y;
}
__device__ __forceinline__ float rcpf(float x) {
    float y; asm("rcp.approx.ftz.f32 %0, %1;" : "=f"(y) : "f"(x)); return y;
}

__global__ void __launch_bounds__(Dn, 1) ltc_kernel(
    const float* __restrict__ X,       // (B,T,d)
    const float* __restrict__ in_w,    // (d)
    const float* __restrict__ in_b,    // (d)
    const float* __restrict__ out_w,   // (d)
    const float* __restrict__ out_b,   // (d)
    const float* __restrict__ gleak,   // (units)
    const float* __restrict__ vleak,   // (units)
    const float* __restrict__ cm,      // (units)
    const float* __restrict__ w,       // (units,units)
    const float* __restrict__ mu,      // (units,units)
    const float* __restrict__ sigma,   // (units,units)
    const float* __restrict__ erev,    // (units,units)
    const float* __restrict__ sw,      // (d,units)
    const float* __restrict__ smu,     // (d,units)
    const float* __restrict__ ssig,    // (d,units)
    const float* __restrict__ serev,   // (d,units)
    float* __restrict__ out)           // (B,d)
{
    const int j  = threadIdx.x;        // pair index, 0..d-1
    const int b0 = blockIdx.x * 2;     // this thread handles batches b0, b0+1
    const int b1 = b0 + 1;
    const int jc = j + Dn;             // partner unit

    // synapse flat indices (row-major (src, tgt)) — shared by both batches
    const int i_aa = j  * UNITS + j;
    const int i_ca = jc * UNITS + j;
    const int i_cc = jc * UNITS + jc;
    const int i_ac = j  * UNITS + jc;

    // sigmoid((v-mu)*sig) = 0.5 + 0.5*tanh(0.5*sig*v - 0.5*sig*mu)
    float sg, m;
    sg = __ldg(sigma + i_aa); m = __ldg(mu + i_aa);
    const float c1_aa = 0.5f * sg, c0_aa = -0.5f * sg * m;
    sg = __ldg(sigma + i_ca); m = __ldg(mu + i_ca);
    const float c1_ca = 0.5f * sg, c0_ca = -0.5f * sg * m;
    sg = __ldg(sigma + i_cc); m = __ldg(mu + i_cc);
    const float c1_cc = 0.5f * sg, c0_cc = -0.5f * sg * m;
    sg = __ldg(sigma + i_ac); m = __ldg(mu + i_ac);
    const float c1_ac = 0.5f * sg, c0_ac = -0.5f * sg * m;

    const float w2_aa = 0.5f * __ldg(w + i_aa), we2_aa = w2_aa * __ldg(erev + i_aa);
    const float w2_ca = 0.5f * __ldg(w + i_ca), we2_ca = w2_ca * __ldg(erev + i_ca);
    const float w2_cc = 0.5f * __ldg(w + i_cc), we2_cc = w2_cc * __ldg(erev + i_cc);
    const float w2_ac = 0.5f * __ldg(w + i_ac), we2_ac = w2_ac * __ldg(erev + i_ac);

    const int is_a = j * UNITS + j;
    const int is_c = j * UNITS + jc;
    sg = __ldg(ssig + is_a); m = __ldg(smu + is_a);
    const float sc1A = 0.5f * sg, sc0A = -0.5f * sg * m;
    sg = __ldg(ssig + is_c); m = __ldg(smu + is_c);
    const float sc1C = 0.5f * sg, sc0C = -0.5f * sg * m;
    const float sw2A = 0.5f * __ldg(sw + is_a), ser2A = sw2A * __ldg(serev + is_a);
    const float sw2C = 0.5f * __ldg(sw + is_c), ser2C = sw2C * __ldg(serev + is_c);

    const float glA = __ldg(gleak + j),  glC = __ldg(gleak + jc);
    const float vlA = __ldg(vleak + j),  vlC = __ldg(vleak + jc);
    const float cmtA = __ldg(cm + j)  * (float)UNFOLDS;
    const float cmtC = __ldg(cm + jc) * (float)UNFOLDS;

    const float numBaseA = fmaf(glA, vlA, we2_aa + we2_ca) + ser2A;
    const float numBaseC = fmaf(glC, vlC, we2_cc + we2_ac) + ser2C;
    const float denBaseA = cmtA + glA + w2_aa + w2_ca + EPSc + sw2A;
    const float denBaseC = cmtC + glC + w2_cc + w2_ac + EPSc + sw2C;

    const float inw = __ldg(in_w + j), inb = __ldg(in_b + j);
    const float ow  = __ldg(out_w + j), ob = __ldg(out_b + j);

    const float* xp0 = X + ((size_t)b0 * Tn) * Dn + j;
    const float* xp1 = X + ((size_t)b1 * Tn) * Dn + j;

    // carry (num, D) with v = num * rcp(D); v0 = 0 — two independent pairs
    float numA0 = 0.0f, DA0 = 1.0f, numC0 = 0.0f, DC0 = 1.0f;
    float numA1 = 0.0f, DA1 = 1.0f, numC1 = 0.0f, DC1 = 1.0f;

    // ---- software-pipelined sensory state for both pairs ----
    float ths;
    float xt0 = fmaf(__ldg(xp0), inw, inb);
    ths = tanhf_(fmaf(sc1A, xt0, sc0A));
    float nbA0 = fmaf(ser2A, ths, numBaseA);
    float dbA0 = fmaf(sw2A,  ths, denBaseA);
    ths = tanhf_(fmaf(sc1C, xt0, sc0C));
    float nbC0 = fmaf(ser2C, ths, numBaseC);
    float dbC0 = fmaf(sw2C,  ths, denBaseC);

    float xt1 = fmaf(__ldg(xp1), inw, inb);
    ths = tanhf_(fmaf(sc1A, xt1, sc0A));
    float nbA1 = fmaf(ser2A, ths, numBaseA);
    float dbA1 = fmaf(sw2A,  ths, denBaseA);
    ths = tanhf_(fmaf(sc1C, xt1, sc0C));
    float nbC1 = fmaf(ser2C, ths, numBaseC);
    float dbC1 = fmaf(sw2C,  ths, denBaseC);

    float xnext0 = __ldg(xp0 + Dn);
    float xnext1 = __ldg(xp1 + Dn);

    #pragma unroll 2
    for (int t = 0; t < Tn; ++t) {
        // ---- NEXT timestep's sensory bases for both pairs ----
        const float xtn0 = fmaf(xnext0, inw, inb);
        const float thsA0n = tanhf_(fmaf(sc1A, xtn0, sc0A));
        const float thsC0n = tanhf_(fmaf(sc1C, xtn0, sc0C));
        const float nbA0_n = fmaf(ser2A, thsA0n, numBaseA);
        const float dbA0_n = fmaf(sw2A,  thsA0n, denBaseA);
        const float nbC0_n = fmaf(ser2C, thsC0n, numBaseC);
        const float dbC0_n = fmaf(sw2C,  thsC0n, denBaseC);

        const float xtn1 = fmaf(xnext1, inw, inb);
        const float thsA1n = tanhf_(fmaf(sc1A, xtn1, sc0A));
        const float thsC1n = tanhf_(fmaf(sc1C, xtn1, sc0C));
        const float nbA1_n = fmaf(ser2A, thsA1n, numBaseA);
        const float dbA1_n = fmaf(sw2A,  thsA1n, denBaseA);
        const float nbC1_n = fmaf(ser2C, thsC1n, numBaseC);
        const float dbC1_n = fmaf(sw2C,  thsC1n, denBaseC);

        {   // branchless prefetch of x for t+2
            const int tnn = (t + 2 < Tn) ? (t + 2) : (Tn - 1);
            xnext0 = __ldg(xp0 + tnn * Dn);
            xnext1 = __ldg(xp1 + tnn * Dn);
        }

        #pragma unroll
        for (int u = 0; u < UNFOLDS; ++u) {
            // ---------- pair 0 ----------
            const float rdA0 = rcpf(DA0);
            const float rdC0 = rcpf(DC0);
            const float pAA0 = c1_aa * numA0;
            const float pAC0 = c1_ac * numA0;
            const float pmA0 = cmtA * numA0;
            const float pCA0 = c1_ca * numC0;
            const float pCC0 = c1_cc * numC0;
            const float pmC0 = cmtC * numC0;

            const float thAA0 = tanhf_(fmaf(pAA0, rdA0, c0_aa));
            const float thAC0 = tanhf_(fmaf(pAC0, rdA0, c0_ac));
            const float thCA0 = tanhf_(fmaf(pCA0, rdC0, c0_ca));
            const float thCC0 = tanhf_(fmaf(pCC0, rdC0, c0_cc));

            // ---------- pair 1 (independent; fills pair 0's stalls) ----------
            const float rdA1 = rcpf(DA1);
            const float rdC1 = rcpf(DC1);
            const float pAA1 = c1_aa * numA1;
            const float pAC1 = c1_ac * numA1;
            const float pmA1 = cmtA * numA1;
            const float pCA1 = c1_ca * numC1;
            const float pCC1 = c1_cc * numC1;
            const float pmC1 = cmtC * numC1;

            const float thAA1 = tanhf_(fmaf(pAA1, rdA1, c0_aa));
            const float thAC1 = tanhf_(fmaf(pAC1, rdA1, c0_ac));
            const float thCA1 = tanhf_(fmaf(pCA1, rdC1, c0_ca));
            const float thCC1 = tanhf_(fmaf(pCC1, rdC1, c0_cc));

            // ---------- pair 0 accumulate ----------
            const float snA0 = fmaf(pmA0, rdA0, nbA0);
            const float snC0 = fmaf(pmC0, rdC0, nbC0);
            float nA0 = fmaf(we2_aa, thAA0, snA0);
            nA0 = fmaf(we2_ca, thCA0, nA0);
            float dA0 = fmaf(w2_aa, thAA0, dbA0);
            dA0 = fmaf(w2_ca, thCA0, dA0);
            float nC0 = fmaf(we2_cc, thCC0, snC0);
            nC0 = fmaf(we2_ac, thAC0, nC0);
            float dC0 = fmaf(w2_cc, thCC0, dbC0);
            dC0 = fmaf(w2_ac, thAC0, dC0);
            numA0 = nA0; DA0 = dA0;
            numC0 = nC0; DC0 = dC0;

            // ---------- pair 1 accumulate ----------
            const float snA1 = fmaf(pmA1, rdA1, nbA1);
            const float snC1 = fmaf(pmC1, rdC1, nbC1);
            float nA1 = fmaf(we2_aa, thAA1, snA1);
            nA1 = fmaf(we2_ca, thCA1, nA1);
            float dA1 = fmaf(w2_aa, thAA1, dbA1);
            dA1 = fmaf(w2_ca, thCA1, dA1);
            float nC1 = fmaf(we2_cc, thCC1, snC1);
            nC1 = fmaf(we2_ac, thAC1, nC1);
            float dC1 = fmaf(w2_cc, thCC1, dbC1);
            dC1 = fmaf(w2_ac, thAC1, dC1);
            numA1 = nA1; DA1 = dA1;
            numC1 = nC1; DC1 = dC1;
        }

        // rotate pipelined sensory state
        nbA0 = nbA0_n; dbA0 = dbA0_n; nbC0 = nbC0_n; dbC0 = dbC0_n;
        nbA1 = nbA1_n; dbA1 = dbA1_n; nbC1 = nbC1_n; dbC1 = dbC1_n;
    }

    const float vA0 = numA0 * rcpf(DA0);
    const float vA1 = numA1 * rcpf(DA1);
    out[b0 * Dn + j] = fmaf(vA0, ow, ob);
    out[b1 * Dn + j] = fmaf(vA1, ow, ob);
}

extern "C" void kernel_launch(void* const* d_in, const int* in_sizes, int n_in,
                              void* d_out, int out_size) {
    const float* X     = (const float*)d_in[0];
    const float* in_w  = (const float*)d_in[1];
    const float* in_b  = (const float*)d_in[2];
    const float* out_w = (const float*)d_in[3];
    const float* out_b = (const float*)d_in[4];
    const float* gleak = (const float*)d_in[5];
    const float* vleak = (const float*)d_in[6];
    const float* cmp   = (const float*)d_in[7];
    const float* w     = (const float*)d_in[8];
    const float* mu    = (const float*)d_in[9];
    const float* sigma = (const float*)d_in[10];
    const float* erev  = (const float*)d_in[11];
    const float* sw    = (const float*)d_in[12];
    const float* smu   = (const float*)d_in[13];
    const float* ssig  = (const float*)d_in[14];
    const float* serev = (const float*)d_in[15];
    float* out = (float*)d_out;

    const int B = in_sizes[0] / (Tn * Dn);   // 32
    ltc_kernel<<<B / 2, Dn>>>(X, in_w, in_b, out_w, out_b,
                              gleak, vleak, cmp, w, mu, sigma, erev,
                              sw, smu, ssig, serev, out);
}

// round 8
// speedup vs baseline: 1.5163x; 1.5163x over previous
#include <cuda_runtime.h>

// LTC MemoryCell: B=32, T=128, d=128, units=256, ODE_UNFOLDS=6.
// Each (v[b,j], v[b,j+d]) pair is an independent 2-dim recurrence; one thread
// per (b,j), all params in registers. Chain-bound at ~83 cyc/unfold.
//
// R8: shorten the per-unfold critical cycle by replacing rcp(D) (chain ~28cyc)
// with a 2-step Newton refinement (4 FMA, chain ~17) of a carried reciprocal,
// for unfolds u>=2 (seed error small there; u=0,1 keep true rcp since D jumps
// at timestep boundaries / first Euler step).

#define Dn      128
#define UNITS   256
#define Tn      128
#define UNFOLDS 6
#define EPSc    1e-8f

__device__ __forceinline__ float tanhf_(float x) {
    float y; asm("tanh.approx.f32 %0, %1;" : "=f"(y) : "f"(x)); return y;
}
__device__ __forceinline__ float rcpf(float x) {
    float y; asm("rcp.approx.ftz.f32 %0, %1;" : "=f"(y) : "f"(x)); return y;
}

__global__ void __launch_bounds__(Dn, 1) ltc_kernel(
    const float* __restrict__ X,       // (B,T,d)
    const float* __restrict__ in_w,    // (d)
    const float* __restrict__ in_b,    // (d)
    const float* __restrict__ out_w,   // (d)
    const float* __restrict__ out_b,   // (d)
    const float* __restrict__ gleak,   // (units)
    const float* __restrict__ vleak,   // (units)
    const float* __restrict__ cm,      // (units)
    const float* __restrict__ w,       // (units,units)
    const float* __restrict__ mu,      // (units,units)
    const float* __restrict__ sigma,   // (units,units)
    const float* __restrict__ erev,    // (units,units)
    const float* __restrict__ sw,      // (d,units)
    const float* __restrict__ smu,     // (d,units)
    const float* __restrict__ ssig,    // (d,units)
    const float* __restrict__ serev,   // (d,units)
    float* __restrict__ out)           // (B,d)
{
    const int j  = threadIdx.x;        // pair index, 0..d-1
    const int b  = blockIdx.x;         // batch index
    const int jc = j + Dn;             // partner unit

    // synapse flat indices (row-major (src, tgt))
    const int i_aa = j  * UNITS + j;
    const int i_ca = jc * UNITS + j;
    const int i_cc = jc * UNITS + jc;
    const int i_ac = j  * UNITS + jc;

    // sigmoid((v-mu)*sig) = 0.5 + 0.5*tanh(0.5*sig*v - 0.5*sig*mu)
    float sg, m;
    sg = __ldg(sigma + i_aa); m = __ldg(mu + i_aa);
    const float c1_aa = 0.5f * sg, c0_aa = -0.5f * sg * m;
    sg = __ldg(sigma + i_ca); m = __ldg(mu + i_ca);
    const float c1_ca = 0.5f * sg, c0_ca = -0.5f * sg * m;
    sg = __ldg(sigma + i_cc); m = __ldg(mu + i_cc);
    const float c1_cc = 0.5f * sg, c0_cc = -0.5f * sg * m;
    sg = __ldg(sigma + i_ac); m = __ldg(mu + i_ac);
    const float c1_ac = 0.5f * sg, c0_ac = -0.5f * sg * m;

    // w*sigmoid = 0.5*w + (0.5*w)*tanh ; same for w*erev
    const float w2_aa = 0.5f * __ldg(w + i_aa), we2_aa = w2_aa * __ldg(erev + i_aa);
    const float w2_ca = 0.5f * __ldg(w + i_ca), we2_ca = w2_ca * __ldg(erev + i_ca);
    const float w2_cc = 0.5f * __ldg(w + i_cc), we2_cc = w2_cc * __ldg(erev + i_cc);
    const float w2_ac = 0.5f * __ldg(w + i_ac), we2_ac = w2_ac * __ldg(erev + i_ac);

    // sensory synapses: src j -> tgt j (A) and src j -> tgt j+d (C)
    const int is_a = j * UNITS + j;
    const int is_c = j * UNITS + jc;
    sg = __ldg(ssig + is_a); m = __ldg(smu + is_a);
    const float sc1A = 0.5f * sg, sc0A = -0.5f * sg * m;
    sg = __ldg(ssig + is_c); m = __ldg(smu + is_c);
    const float sc1C = 0.5f * sg, sc0C = -0.5f * sg * m;
    const float sw2A = 0.5f * __ldg(sw + is_a), ser2A = sw2A * __ldg(serev + is_a);
    const float sw2C = 0.5f * __ldg(sw + is_c), ser2C = sw2C * __ldg(serev + is_c);

    // per-unit params
    const float glA = __ldg(gleak + j),  glC = __ldg(gleak + jc);
    const float vlA = __ldg(vleak + j),  vlC = __ldg(vleak + jc);
    const float cmtA = __ldg(cm + j)  * (float)UNFOLDS;
    const float cmtC = __ldg(cm + jc) * (float)UNFOLDS;

    // static parts of num/den bases (tanh half-weights folded in; EPS in den)
    const float numBaseA = fmaf(glA, vlA, we2_aa + we2_ca) + ser2A;
    const float numBaseC = fmaf(glC, vlC, we2_cc + we2_ac) + ser2C;
    const float denBaseA = cmtA + glA + w2_aa + w2_ca + EPSc + sw2A;
    const float denBaseC = cmtC + glC + w2_cc + w2_ac + EPSc + sw2C;

    const float inw = __ldg(in_w + j), inb = __ldg(in_b + j);
    const float ow  = __ldg(out_w + j), ob = __ldg(out_b + j);

    const float* xp = X + ((size_t)b * Tn) * Dn + j;

    // carry (num, D) with v = num * rcp(D); v0 = 0
    float numA = 0.0f, DA = 1.0f;
    float numC = 0.0f, DC = 1.0f;

    // ---- software-pipelined sensory state ----
    float xt0 = fmaf(__ldg(xp), inw, inb);
    float ths;
    ths = tanhf_(fmaf(sc1A, xt0, sc0A));
    float nbA = fmaf(ser2A, ths, numBaseA);
    float dbA = fmaf(sw2A,  ths, denBaseA);
    ths = tanhf_(fmaf(sc1C, xt0, sc0C));
    float nbC = fmaf(ser2C, ths, numBaseC);
    float dbC = fmaf(sw2C,  ths, denBaseC);

    float xnext = __ldg(xp + Dn);        // raw x for t=1

    #pragma unroll 2
    for (int t = 0; t < Tn; ++t) {
        // ---- NEXT timestep's sensory bases (independent of v) ----
        const float xtn = fmaf(xnext, inw, inb);
        const float thsA_n = tanhf_(fmaf(sc1A, xtn, sc0A));
        const float thsC_n = tanhf_(fmaf(sc1C, xtn, sc0C));
        const float nbA_n = fmaf(ser2A, thsA_n, numBaseA);
        const float dbA_n = fmaf(sw2A,  thsA_n, denBaseA);
        const float nbC_n = fmaf(ser2C, thsC_n, numBaseC);
        const float dbC_n = fmaf(sw2C,  thsC_n, denBaseC);
        {   // branchless prefetch of x for t+2
            const int tnn = (t + 2 < Tn) ? (t + 2) : (Tn - 1);
            xnext = __ldg(xp + tnn * Dn);
        }

        float rA = 1.0f, rC = 1.0f;     // carried reciprocal approximations

        #pragma unroll
        for (int u = 0; u < UNFOLDS; ++u) {
            float rdA, rdC;
            if (u < 2) {
                // D jumps at timestep boundary (u=0) and first Euler step
                // (u=1): use the true MUFU rcp.
                rdA = rcpf(DA);
                rdC = rcpf(DC);
            } else {
                // 2-step Newton from the previous unfold's reciprocal:
                // chain 4 FMA (~17cyc) instead of rcp (~28cyc).
                float eA = fmaf(-DA, rA, 1.0f);
                rdA = fmaf(rA, eA, rA);
                float eA2 = fmaf(-DA, rdA, 1.0f);
                rdA = fmaf(rdA, eA2, rdA);
                float eC = fmaf(-DC, rC, 1.0f);
                rdC = fmaf(rC, eC, rC);
                float eC2 = fmaf(-DC, rdC, 1.0f);
                rdC = fmaf(rdC, eC2, rdC);
            }
            rA = rdA; rC = rdC;

            // multipliers computed in the reciprocal's shadow
            const float pAA = c1_aa * numA;
            const float pAC = c1_ac * numA;
            const float pmA = cmtA * numA;
            const float pCA = c1_ca * numC;
            const float pCC = c1_cc * numC;
            const float pmC = cmtC * numC;

            const float thAA = tanhf_(fmaf(pAA, rdA, c0_aa));
            const float thAC = tanhf_(fmaf(pAC, rdA, c0_ac));
            const float thCA = tanhf_(fmaf(pCA, rdC, c0_ca));
            const float thCC = tanhf_(fmaf(pCC, rdC, c0_cc));

            // early partial sums (ready before tanh results)
            const float snA = fmaf(pmA, rdA, nbA);
            const float snC = fmaf(pmC, rdC, nbC);

            float nA = fmaf(we2_aa, thAA, snA);
            nA = fmaf(we2_ca, thCA, nA);
            float dA = fmaf(w2_aa, thAA, dbA);
            dA = fmaf(w2_ca, thCA, dA);

            float nC = fmaf(we2_cc, thCC, snC);
            nC = fmaf(we2_ac, thAC, nC);
            float dC = fmaf(w2_cc, thCC, dbC);
            dC = fmaf(w2_ac, thAC, dC);

            numA = nA; DA = dA;
            numC = nC; DC = dC;
        }

        // rotate pipelined sensory state
        nbA = nbA_n; dbA = dbA_n;
        nbC = nbC_n; dbC = dbC_n;
    }

    const float vA = numA * rcpf(DA);
    out[b * Dn + j] = fmaf(vA, ow, ob);
}

extern "C" void kernel_launch(void* const* d_in, const int* in_sizes, int n_in,
                              void* d_out, int out_size) {
    const float* X     = (const float*)d_in[0];
    const float* in_w  = (const float*)d_in[1];
    const float* in_b  = (const float*)d_in[2];
    const float* out_w = (const float*)d_in[3];
    const float* out_b = (const float*)d_in[4];
    const float* gleak = (const float*)d_in[5];
    const float* vleak = (const float*)d_in[6];
    const float* cmp   = (const float*)d_in[7];
    const float* w     = (const float*)d_in[8];
    const float* mu    = (const float*)d_in[9];
    const float* sigma = (const float*)d_in[10];
    const float* erev  = (const float*)d_in[11];
    const float* sw    = (const float*)d_in[12];
    const float* smu   = (const float*)d_in[13];
    const float* ssig  = (const float*)d_in[14];
    const float* serev = (const float*)d_in[15];
    float* out = (float*)d_out;

    const int B = in_sizes[0] / (Tn * Dn);   // 32
    ltc_kernel<<<B, Dn>>>(X, in_w, in_b, out_w, out_b,
                          gleak, vleak, cmp, w, mu, sigma, erev,
                          sw, smu, ssig, serev, out);
}